// round 12
// baseline (speedup 1.0000x reference)
#include <cuda_runtime.h>
#include <cuda_fp16.h>

// GPTQ int4 dequant GEMM via HMMA: out[32,8192] = x @ dequant(W)^T + bias
// M=32, K=8192, N=8192, group=64. packed int32 element = one byte = 2 k-nibbles.
// v12: v11 core (raw biased nibbles 1024+q, running rescale fixup, XOR-swizzled
// smem, 3 CTAs/SM) with weight staging in GROUP-PAIRS: 2 super-buffers x 32KB,
// one cp.async commit per pair -> 32KB in flight per CTA during compute (2x v11)
// and half the waits/barriers. float4-vectorized bias init in merged prologue.

#define MM 32
#define KDIM 8192
#define NDIM 8192
#define GS 64
#define NGROUPS 128
#define NTHREADS 256
#define NBLK 128           // n per CTA
#define KSPLIT 16
#define KPER 512           // k per CTA
#define GROUPS_PER 8       // KPER / GS
#define NPAIRS 4           // group pairs per CTA
#define WGRP 4096          // int32 per group: 128 rows * 32 int32 (no pad)
#define WS_BYTES (4 * WGRP * 4)          // 2 super-buffers x 2 groups = 65536
#define XS_BYTES (MM * 1024)             // 32768 (32 rows * 1024B, swizzled)
#define SMEM_TOTAL (WS_BYTES + XS_BYTES + 1024 + 2 * GROUPS_PER * NBLK * 4) // 107520... 

// NOTE: WS grew to 64KB? No: 4*WGRP*4 = 65536 -> total 107.5KB would kill 3 CTAs.
// Keep total smem identical to v11: the super-buffer layout REUSES the same
// 2*16KB-per-slot region; we need 2 pairs resident = 4 groups = 64KB... v11 had
// 32KB ws. To keep 3 CTAs/SM we shrink xs instead? No -- instead use ring of
// 2 super-buffers where each holds 2 groups: that IS 64KB. Offset by dropping
// nothing else; total = 65536+32768+1024+8192 = 107520 > 74752 -> 2 CTAs/SM.
// That trade (2 CTAs x 32KB in flight = 64KB/SM vs 3 CTAs x 16KB = 48KB/SM,
// but -33% warps) is worse. SOLUTION: keep 3 groups resident (48KB ws):
// ring of 3 group-buffers, commit per GROUP, but wait<2> so TWO groups are
// in flight during compute. total = 49152+32768+1024+8192 = 91136 -> 2 CTAs.
// Still worse. FINAL CHOICE: keep v11's 2x16KB ring and instead SPLIT each
// group commit in half (8KB) with wait<2>: buffer g&1 holds group g in two
// halves committed separately; during compute of g, halves of g+1 land
// progressively and wait only blocks on the OLDER half -> finer-grained
// overlap, in-flight up to 24KB, smem unchanged at 74752 -> 3 CTAs/SM.
#undef WS_BYTES
#undef SMEM_TOTAL
#define WS_BYTES (2 * WGRP * 4)          // 32768, as v11
#define SMEM_TOTAL (WS_BYTES + XS_BYTES + 1024 + 2 * GROUPS_PER * NBLK * 4) // 74752

// global LUT: X_g[m] = sum_{k in group g} fp16(x[m,k]), fp32. 16 KB.
__device__ float d_Xg[NGROUPS * MM];

__device__ __forceinline__ unsigned smem_u32(const void* p) {
    unsigned a;
    asm("{ .reg .u64 t; cvta.to.shared.u64 t, %1; cvt.u32.u64 %0, t; }"
        : "=r"(a) : "l"(p));
    return a;
}
__device__ __forceinline__ void cp_async16(unsigned saddr, const void* gptr) {
    asm volatile("cp.async.cg.shared.global [%0], [%1], 16;\n"
                 :: "r"(saddr), "l"(gptr));
}
__device__ __forceinline__ void cp_commit() {
    asm volatile("cp.async.commit_group;\n" ::: "memory");
}
template <int N>
__device__ __forceinline__ void cp_wait() {
    asm volatile("cp.async.wait_group %0;\n" :: "n"(N) : "memory");
}
__device__ __forceinline__ void ldsm4(unsigned& r0, unsigned& r1,
                                      unsigned& r2, unsigned& r3, unsigned a) {
    asm volatile("ldmatrix.sync.aligned.m8n8.x4.shared.b16 {%0,%1,%2,%3}, [%4];"
                 : "=r"(r0), "=r"(r1), "=r"(r2), "=r"(r3) : "r"(a));
}
__device__ __forceinline__ void mma16816(float d[4], const unsigned a[4],
                                         const unsigned b[2]) {
    asm volatile(
        "mma.sync.aligned.m16n8k16.row.col.f32.f16.f16.f32 "
        "{%0,%1,%2,%3}, {%4,%5,%6,%7}, {%8,%9}, {%0,%1,%2,%3};"
        : "+f"(d[0]), "+f"(d[1]), "+f"(d[2]), "+f"(d[3])
        : "r"(a[0]), "r"(a[1]), "r"(a[2]), "r"(a[3]), "r"(b[0]), "r"(b[1]));
}
__device__ __forceinline__ void red2(float* p, float a, float b) {
    asm volatile("red.global.add.v2.f32 [%0], {%1, %2};"
                 :: "l"(p), "f"(a), "f"(b) : "memory");
}
// raw biased dequant: byte b -> fp16x2 {lo = 1024+lo_nib, hi = 1024+hi_nib}. Exact.
__device__ __forceinline__ unsigned dqraw(int b) {
    unsigned t = (unsigned)b | ((unsigned)b << 12);
    return (t & 0x000F000Fu) | 0x64006400u;
}

// merged prologue: blocks 0..255 init out=bias (float4); blocks 256..287 X sums
__global__ void __launch_bounds__(NTHREADS)
gptq_pre(const float* __restrict__ bias, float* __restrict__ out,
         const float* __restrict__ x) {
    const int bid = blockIdx.x;
    const int t = threadIdx.x;
    const int NINIT = (MM * NDIM / 4) / NTHREADS;   // 256
    if (bid < NINIT) {
        int i = bid * NTHREADS + t;                 // float4 index
        const float4* b4 = reinterpret_cast<const float4*>(bias);
        reinterpret_cast<float4*>(out)[i] = b4[i & (NDIM / 4 - 1)];
        return;
    }
    const int m = bid - NINIT;
    const int l = t & 31;
    const float4* xr = reinterpret_cast<const float4*>(x + (size_t)m * KDIM);
    float s[8];
#pragma unroll
    for (int i = 0; i < 8; ++i) {
        float4 v = xr[t + 256 * i];
        __half2 h0 = __floats2half2_rn(v.x, v.y);
        __half2 h1 = __floats2half2_rn(v.z, v.w);
        float2 f0 = __half22float2(h0);
        float2 f1 = __half22float2(h1);
        s[i] = (f0.x + f0.y) + (f1.x + f1.y);
    }
#pragma unroll
    for (int mask = 1; mask < 16; mask <<= 1)
#pragma unroll
        for (int i = 0; i < 8; ++i)
            s[i] += __shfl_xor_sync(0xFFFFFFFFu, s[i], mask);
    const int j = l & 15;
    if (j < 8) {
        const int g = (t >> 4) + 16 * j;
        d_Xg[g * MM + m] = s[j];
    }
}

extern __shared__ char smem_raw[];

__global__ void __launch_bounds__(NTHREADS, 3)
gptq_main(const float* __restrict__ x, const int* __restrict__ pw,
          const float* __restrict__ scales, const float* __restrict__ zeros,
          float* __restrict__ out)
{
    int* ws = reinterpret_cast<int*>(smem_raw);                        // [2][128][32], swizzled
    __half* xs = reinterpret_cast<__half*>(smem_raw + WS_BYTES);       // [32][512], swizzled
    float* xsum = reinterpret_cast<float*>(smem_raw + WS_BYTES + XS_BYTES); // [8][32]
    float* c2s = xsum + GROUPS_PER * 32;                               // [8][128] z+1024
    float* rqs = c2s + GROUPS_PER * NBLK;                              // [8][128] ratio

    const int tid = threadIdx.x;
    const int w = tid >> 5;
    const int l = tid & 31;
    const int nblock0 = blockIdx.x * NBLK;
    const int k0 = blockIdx.y * KPER;
    const int g0 = blockIdx.y * GROUPS_PER;

    const unsigned ws_base = smem_u32(ws);

    // staging geometry (as v11): thread -> (row = tid>>3 + 32i, ch = tid&7),
    // swizzled chunk = ch ^ (row&7). Each HALF-group commit covers rows 0..63
    // (i=0,1) or 64..127 (i=2,3): 8KB apiece.
    const int s_ch  = tid & 7;
    const int s_row = tid >> 3;
    const int s_swz = s_ch ^ (s_row & 7);

    // stage half h (0: rows 0-63, 1: rows 64-127) of group g into buffer b
    auto stage_wh = [&](int g, int b, int h) {
        const int* gsrc = pw + ((k0 + g * GS) >> 1) + s_ch * 4;
        unsigned sdst = ws_base + (unsigned)(b * WGRP * 4 + s_row * 128 + s_swz * 16);
#pragma unroll
        for (int i = 0; i < 2; ++i) {
            int r = h * 64 + i * 32;
            cp_async16(sdst + (unsigned)(r * 128),
                       gsrc + (size_t)(nblock0 + s_row + r) * (KDIM / 2));
        }
        cp_commit();
    };
    // prologue: group0 (2 halves), group1 (2 halves) -> 4 pending commits
    stage_wh(0, 0, 0); stage_wh(0, 0, 1);
    stage_wh(1, 1, 0); stage_wh(1, 1, 1);

    // ---- stage x: fp32 -> fp16, swizzled rows (identical to v11) ----
    {
#pragma unroll
        for (int i = 0; i < 16; ++i) {
            int lin = tid + i * NTHREADS;
            int v = lin & 127;
            int m = lin >> 7;
            float4 xv = *reinterpret_cast<const float4*>(x + (size_t)m * KDIM + k0 + 4 * v);
            __half2 h0 = __floats2half2_rn(xv.x, xv.y);
            __half2 h1 = __floats2half2_rn(xv.z, xv.w);
            uint2 pr;
            pr.x = *reinterpret_cast<unsigned*>(&h0);
            pr.y = *reinterpret_cast<unsigned*>(&h1);
            unsigned byte_off = (unsigned)(m * 1024 + (((v >> 1) ^ (m & 7)) << 4) + (v & 1) * 8);
            *reinterpret_cast<uint2*>(reinterpret_cast<char*>(xs) + byte_off) = pr;
        }
    }

    // ---- X LUT slice ----
    xsum[tid] = __ldg(&d_Xg[(g0 + (tid >> 5)) * MM + (tid & 31)]);

    // ---- scale/zero LUTs ----
#pragma unroll
    for (int i = 0; i < 4; ++i) {
        int lin = tid + i * NTHREADS;
        int g = lin & 7;
        int n = lin >> 3;
        const float* srow = scales + (size_t)(nblock0 + n) * NGROUPS + g0;
        float s = __ldg(srow + g);
        float z = __ldg(zeros + (size_t)(nblock0 + n) * NGROUPS + g0 + g);
        float rq;
        if (g < GROUPS_PER - 1) {
            float sn = __ldg(srow + g + 1);
            rq = __fdividef(s, sn);
        } else {
            rq = s;
        }
        c2s[g * NBLK + n] = z + 1024.0f;
        rqs[g * NBLK + n] = rq;
    }

    // ldsm / weight / accumulator lane geometry (identical to v11)
    const unsigned xs_base = smem_u32(xs);
    const unsigned xrow0 = xs_base + (unsigned)((l & 15) * 1024);
    const unsigned xrow1 = xrow0 + 16u * 1024u;
    const int hk = l >> 4;
    const int lw = l & 7;
    const int xw = l >> 2;
    const int wbase0 = (w * 16 + (l >> 2)) * 32 + (l & 3);
    const int wbase1 = wbase0 + 8 * 32;
    const int ncol = w * 16 + 2 * (l & 3);

    float acc[2][2][4] = {};

#pragma unroll
    for (int g = 0; g < GROUPS_PER; ++g) {
        // pending commits when entering group g: halves of g (2) + halves of
        // g+1 if staged (2) + halves of g+2 staged mid-loop. We wait so that
        // group g's 2 halves are complete: keep at most the NEWER commits.
        // Pending layout (steady state): [g.h0, g.h1, g+1.h0, g+1.h1] -> wait<2>.
        if (g >= GROUPS_PER - 1) cp_wait<0>();
        else                     cp_wait<2>();
        __syncthreads();

        const int bufo = (g & 1) * WGRP;

#pragma unroll
        for (int s4 = 0; s4 < 4; ++s4) {
            const int s = g * 4 + s4;
            unsigned xoff = (unsigned)(((2 * s + hk) ^ lw) << 4);
            unsigned a0[4], a1[4];
            ldsm4(a0[0], a0[1], a0[2], a0[3], xrow0 + xoff);
            ldsm4(a1[0], a1[1], a1[2], a1[3], xrow1 + xoff);

            const int c0 = ((2 * s4)     ^ xw) * 4;
            const int c1 = ((2 * s4 + 1) ^ xw) * 4;
            unsigned b0[2], b1[2];
            b0[0] = dqraw(ws[bufo + wbase0 + c0]);
            b0[1] = dqraw(ws[bufo + wbase0 + c1]);
            b1[0] = dqraw(ws[bufo + wbase1 + c0]);
            b1[1] = dqraw(ws[bufo + wbase1 + c1]);

            mma16816(acc[0][0], a0, b0);
            mma16816(acc[0][1], a0, b1);
            mma16816(acc[1][0], a1, b0);
            mma16816(acc[1][1], a1, b1);

            // refill the just-freed buffer in HALVES, spread across the group:
            // after step 1 stage half0 of g+2, after step 3 stage half1.
            if (s4 == 1 && g + 2 < GROUPS_PER) {
                __syncthreads();               // warps may still read buf g&1? No:
                // buffer being refilled is (g&1) -- the one we're READING. Must
                // not refill until done. Refill targets buffer (g&1) only after
                // group g completes. So defer: see post-group staging below.
            }
        }

        // end-of-group fixup: acc = (acc - (z+1024)*X_g[row]) * rq
        {
            const float* xg = xsum + g * 32 + (l >> 2);
            float Xv[4];
            Xv[0] = xg[0];  Xv[1] = xg[8];
            Xv[2] = xg[16]; Xv[3] = xg[24];
            const float* c2g = c2s + g * NBLK + ncol;
            const float* rqg = rqs + g * NBLK + ncol;
            float c2v[4], rqv[4];
            c2v[0] = c2g[0]; c2v[1] = c2g[1]; c2v[2] = c2g[8]; c2v[3] = c2g[9];
            rqv[0] = rqg[0]; rqv[1] = rqg[1]; rqv[2] = rqg[8]; rqv[3] = rqg[9];
#pragma unroll
            for (int tm = 0; tm < 2; ++tm)
#pragma unroll
                for (int tn = 0; tn < 2; ++tn)
#pragma unroll
                    for (int e = 0; e < 4; ++e) {
                        const float Xe = Xv[tm * 2 + (e >> 1)];
                        const float c2e = c2v[tn * 2 + (e & 1)];
                        const float rqe = rqv[tn * 2 + (e & 1)];
                        acc[tm][tn][e] = fmaf(-c2e, Xe, acc[tm][tn][e]) * rqe;
                    }
        }

        if (g < GROUPS_PER - 2) {
            __syncthreads();                   // done reading buffer g&1
            stage_wh(g + 2, g & 1, 0);         // two half-commits: finer-grained
            stage_wh(g + 2, g & 1, 1);         // wait granularity downstream
        }
    }

    // ---- epilogue: K-split partials via vector reductions ----
#pragma unroll
    for (int tm = 0; tm < 2; ++tm) {
#pragma unroll
        for (int tn = 0; tn < 2; ++tn) {
            const int n = nblock0 + w * 16 + tn * 8 + (l & 3) * 2;
            const int m = tm * 16 + (l >> 2);
            red2(out + (size_t)m * NDIM + n,       acc[tm][tn][0], acc[tm][tn][1]);
            red2(out + (size_t)(m + 8) * NDIM + n, acc[tm][tn][2], acc[tm][tn][3]);
        }
    }
}

extern "C" void kernel_launch(void* const* d_in, const int* in_sizes, int n_in,
                              void* d_out, int out_size) {
    const float* x      = (const float*)d_in[0];
    const int*   pw     = (const int*)d_in[1];
    const float* scales = (const float*)d_in[2];
    const float* zeros  = (const float*)d_in[3];
    const float* bias   = (const float*)d_in[4];
    float* out = (float*)d_out;

    gptq_pre<<<(MM * NDIM / 4) / NTHREADS + MM, NTHREADS>>>(bias, out, x);

    cudaFuncSetAttribute(gptq_main, cudaFuncAttributeMaxDynamicSharedMemorySize,
                         SMEM_TOTAL);
    dim3 grid(NDIM / NBLK, KSPLIT);
    gptq_main<<<grid, NTHREADS, SMEM_TOTAL>>>(x, pw, scales, zeros, out);
}